// round 2
// baseline (speedup 1.0000x reference)
#include <cuda_runtime.h>

#define NG      512
#define NODES   200
#define EDGES   6400
#define HID     128
#define TPB     512

// MLP intermediate buffers (no cudaMalloc allowed)
__device__ float g_hg[NG * HID];
__device__ float g_x1[NG * 512];
__device__ float g_x2[NG * 1024];
__device__ float g_x3[NG * 1024];
__device__ float g_x4[NG * 512];

// ---------------------------------------------------------------------------
// Per-graph GNN kernel, one CTA (512 threads) per graph, everything in SMEM.
// SMEM layout (floats):
//   bufA[200*128]  : hv, later h2
//   bufB[200*128]  : t = (hv@W2)*inv_out, later pool partials
//   s_s/s_a/s_ii/s_io[200]
//   Wt[16*128]     : staged W2 k-tile
//   ints: cnt[204], cur[204], odeg[204]
//   csr : uint8[6400] (src local ids, grouped by dst)
// Total = 225,040 bytes
// ---------------------------------------------------------------------------
__global__ void __launch_bounds__(TPB, 1) gnn_kernel(
    const int*   __restrict__ src, const int*   __restrict__ dst,
    const float* __restrict__ W1,  const float* __restrict__ b1,
    const float* __restrict__ W2,  const float* __restrict__ b2,
    float* __restrict__ hg)
{
    extern __shared__ float sf[];
    float* bufA = sf;                       // 25600 floats
    float* bufB = sf + NODES * HID;         // 25600 floats
    float* s_s  = sf + 2 * NODES * HID;     // 200
    float* s_a  = s_s + NODES;              // 200
    float* s_ii = s_a + NODES;              // 200
    float* s_io = s_ii + NODES;             // 200
    float* Wt   = s_io + NODES;             // 2048 floats (16x128)
    int*   cnt  = (int*)(Wt + 2048);        // 204
    int*   cur  = cnt + 204;                // 204
    int*   odeg = cur + 204;                // 204
    unsigned char* csr = (unsigned char*)(odeg + 204); // 6400 bytes

    const int tid   = threadIdx.x;
    const int g     = blockIdx.x;
    const int ebase = g * EDGES;
    const int nbase = g * NODES;

    // --- degrees ---
    for (int i = tid; i < NODES; i += TPB) { cnt[i] = 0; odeg[i] = 0; }
    __syncthreads();
    for (int e = tid; e < EDGES; e += TPB) {
        int sl = src[ebase + e] - nbase;
        int dl = dst[ebase + e] - nbase;
        atomicAdd(&cnt[dl], 1);
        atomicAdd(&odeg[sl], 1);
    }
    __syncthreads();
    for (int i = tid; i < NODES; i += TPB) {
        float idg = (float)cnt[i];
        float odg = (float)odeg[i];
        float ii = rsqrtf(fmaxf(idg, 1.0f));
        float io = rsqrtf(fmaxf(odg, 1.0f));
        s_ii[i] = ii;
        s_io[i] = io;
        s_s[i]  = idg * io;      // layer-1 per-src scalar
    }
    __syncthreads();
    // --- warp-parallel exclusive scan of in-degree counts (warp 0) ---
    if (tid < 32) {
        const int PER = 7;                        // 32*7 = 224 >= 200
        int base = tid * PER;
        int vals[PER];
        int s = 0;
        #pragma unroll
        for (int j = 0; j < PER; j++) {
            int i = base + j;
            int c = (i < NODES) ? cnt[i] : 0;
            vals[j] = c; s += c;
        }
        int pre = s;
        #pragma unroll
        for (int o = 1; o < 32; o <<= 1) {
            int t = __shfl_up_sync(0xffffffffu, pre, o);
            if (tid >= o) pre += t;
        }
        int run = pre - s;                        // exclusive prefix
        #pragma unroll
        for (int j = 0; j < PER; j++) {
            int i = base + j;
            if (i < NODES) { cnt[i] = run; cur[i] = run; run += vals[j]; }
        }
        if (tid == 31) cnt[NODES] = run;
    }
    __syncthreads();
    // --- CSR fill: src local ids grouped by dst ---
    for (int e = tid; e < EDGES; e += TPB) {
        int sl = src[ebase + e] - nbase;
        int dl = dst[ebase + e] - nbase;
        int p  = atomicAdd(&cur[dl], 1);
        csr[p] = (unsigned char)sl;
    }
    __syncthreads();
    // --- layer-1 aggregation (scalar per dst) ---
    for (int d = tid; d < NODES; d += TPB) {
        float sum = 0.0f;
        int p0 = cnt[d], p1 = cnt[d + 1];
        for (int p = p0; p < p1; p++) sum += s_s[csr[p]];
        s_a[d] = sum * s_ii[d];
    }
    __syncthreads();
    // --- hv[i][k] = relu(a[i]*W1[k] + b1[k]) into bufA ---
    {
        const float4* W1v = (const float4*)W1;
        const float4* b1v = (const float4*)b1;
        for (int idx = tid; idx < NODES * 32; idx += TPB) {
            int i = idx >> 5, k4 = idx & 31;
            float av = s_a[i];
            float4 w = W1v[k4], bb = b1v[k4];
            float4 h;
            h.x = fmaxf(fmaf(av, w.x, bb.x), 0.0f);
            h.y = fmaxf(fmaf(av, w.y, bb.y), 0.0f);
            h.z = fmaxf(fmaf(av, w.z, bb.z), 0.0f);
            h.w = fmaxf(fmaf(av, w.w, bb.w), 0.0f);
            ((float4*)bufA)[idx] = h;
        }
    }
    __syncthreads();
    // --- GEMM: bufB[i][j] = inv_out[i] * sum_k bufA[i][k] * W2[k][j] ---
    const int tx = tid & 31;   // 32 float4 column groups -> 128 cols
    const int ty = tid >> 5;   // 16 warps
    const float4* W2v = (const float4*)W2;
    float4* Wt4 = (float4*)Wt;
    for (int rb = 0; rb < 4; ++rb) {                 // 4 x 64 rows
        int r[4], rc[4];
        #pragma unroll
        for (int m = 0; m < 4; m++) {
            r[m]  = rb * 64 + m * 16 + ty;
            rc[m] = (r[m] < NODES) ? r[m] : 0;
        }
        float4 acc[4] = {{0,0,0,0},{0,0,0,0},{0,0,0,0},{0,0,0,0}};
        for (int kt = 0; kt < 8; ++kt) {
            Wt4[tid] = W2v[kt * 512 + tid];          // stage 16x128 tile
            __syncthreads();
            #pragma unroll
            for (int kk = 0; kk < 16; kk += 4) {
                float4 a4[4];
                #pragma unroll
                for (int m = 0; m < 4; m++)
                    a4[m] = *(const float4*)(bufA + rc[m] * HID + kt * 16 + kk);
                #pragma unroll
                for (int q = 0; q < 4; q++) {
                    float4 w = Wt4[(kk + q) * 32 + tx];
                    #pragma unroll
                    for (int m = 0; m < 4; m++) {
                        float av = ((const float*)&a4[m])[q];
                        acc[m].x = fmaf(av, w.x, acc[m].x);
                        acc[m].y = fmaf(av, w.y, acc[m].y);
                        acc[m].z = fmaf(av, w.z, acc[m].z);
                        acc[m].w = fmaf(av, w.w, acc[m].w);
                    }
                }
            }
            __syncthreads();
        }
        #pragma unroll
        for (int m = 0; m < 4; m++) {
            if (r[m] < NODES) {
                float io = s_io[r[m]];
                float4 o = acc[m];
                o.x *= io; o.y *= io; o.z *= io; o.w *= io;
                ((float4*)bufB)[r[m] * 32 + tx] = o;
            }
        }
    }
    __syncthreads();
    // --- layer-2 aggregation: h2[d] = relu((sum_{e->d} t[src]) * inv_in[d] + b2)
    {
        float4 bb2 = ((const float4*)b2)[tx];
        for (int d = ty; d < NODES; d += 16) {        // warp per dst
            int p0 = cnt[d], p1 = cnt[d + 1];
            float4 acc = {0, 0, 0, 0};
            for (int p = p0; p < p1; ++p) {
                int sv = csr[p];
                float4 v = ((const float4*)bufB)[sv * 32 + tx];
                acc.x += v.x; acc.y += v.y; acc.z += v.z; acc.w += v.w;
            }
            float ii = s_ii[d];
            float4 h;
            h.x = fmaxf(fmaf(acc.x, ii, bb2.x), 0.0f);
            h.y = fmaxf(fmaf(acc.y, ii, bb2.y), 0.0f);
            h.z = fmaxf(fmaf(acc.z, ii, bb2.z), 0.0f);
            h.w = fmaxf(fmaf(acc.w, ii, bb2.w), 0.0f);
            ((float4*)bufA)[d * 32 + tx] = h;
        }
    }
    __syncthreads();
    // --- mean pool over 200 nodes (16 warp partials, then warp 0 reduce) ---
    {
        float4 acc = {0, 0, 0, 0};
        for (int r = ty; r < NODES; r += 16) {
            float4 v = ((const float4*)bufA)[r * 32 + tx];
            acc.x += v.x; acc.y += v.y; acc.z += v.z; acc.w += v.w;
        }
        ((float4*)bufB)[ty * 32 + tx] = acc;
    }
    __syncthreads();
    if (tid < 32) {
        float4 t = {0, 0, 0, 0};
        #pragma unroll
        for (int c = 0; c < 16; c++) {
            float4 v = ((const float4*)bufB)[c * 32 + tid];
            t.x += v.x; t.y += v.y; t.z += v.z; t.w += v.w;
        }
        const float inv = 1.0f / 200.0f;
        t.x *= inv; t.y *= inv; t.z *= inv; t.w *= inv;
        ((float4*)(hg + g * HID))[tid] = t;
    }
}

// ---------------------------------------------------------------------------
// Tiled fp32 GEMM: C = relu(A @ W + bias). 64x64 tile, 512 threads,
// each thread 2 rows x 1 float4 (8 outputs). M%64==0, Nc%64==0, K%16==0.
// ---------------------------------------------------------------------------
__global__ void __launch_bounds__(512) gemm_bias_relu(
    const float* __restrict__ A, const float* __restrict__ W,
    const float* __restrict__ bias, float* __restrict__ C,
    int M, int K, int Nc)
{
    __shared__ float As[64 * 16];
    __shared__ float Ws[16 * 64];
    const int tid = threadIdx.x;
    const int tx = tid & 15;        // 16 float4 col groups -> 64 cols
    const int ty = tid >> 4;        // 32 row pairs -> 64 rows
    const int row0 = blockIdx.y * 64, col0 = blockIdx.x * 64;

    float4 acc0 = {0,0,0,0}, acc1 = {0,0,0,0};

    for (int kt = 0; kt < K; kt += 16) {
        if (tid < 256) {            // A tile 64x16 = 256 float4
            int r = tid >> 2, kq = tid & 3;
            ((float4*)As)[tid] = *(const float4*)(A + (size_t)(row0 + r) * K + kt + kq * 4);
        } else {                    // W tile 16x64 = 256 float4
            int t2 = tid - 256;
            int kk = t2 >> 4, cq = t2 & 15;
            ((float4*)Ws)[t2] = *(const float4*)(W + (size_t)(kt + kk) * Nc + col0 + cq * 4);
        }
        __syncthreads();
        #pragma unroll
        for (int kk = 0; kk < 16; kk++) {
            float4 w = ((float4*)Ws)[kk * 16 + tx];
            float a0 = As[(ty * 2 + 0) * 16 + kk];
            float a1 = As[(ty * 2 + 1) * 16 + kk];
            acc0.x = fmaf(a0, w.x, acc0.x);
            acc0.y = fmaf(a0, w.y, acc0.y);
            acc0.z = fmaf(a0, w.z, acc0.z);
            acc0.w = fmaf(a0, w.w, acc0.w);
            acc1.x = fmaf(a1, w.x, acc1.x);
            acc1.y = fmaf(a1, w.y, acc1.y);
            acc1.z = fmaf(a1, w.z, acc1.z);
            acc1.w = fmaf(a1, w.w, acc1.w);
        }
        __syncthreads();
    }
    float4 bv = *(const float4*)(bias + col0 + tx * 4);
    float4 o0 = acc0, o1 = acc1;
    o0.x = fmaxf(o0.x + bv.x, 0.0f); o0.y = fmaxf(o0.y + bv.y, 0.0f);
    o0.z = fmaxf(o0.z + bv.z, 0.0f); o0.w = fmaxf(o0.w + bv.w, 0.0f);
    o1.x = fmaxf(o1.x + bv.x, 0.0f); o1.y = fmaxf(o1.y + bv.y, 0.0f);
    o1.z = fmaxf(o1.z + bv.z, 0.0f); o1.w = fmaxf(o1.w + bv.w, 0.0f);
    *(float4*)(C + (size_t)(row0 + ty * 2 + 0) * Nc + col0 + tx * 4) = o0;
    *(float4*)(C + (size_t)(row0 + ty * 2 + 1) * Nc + col0 + tx * 4) = o1;
}

// ---------------------------------------------------------------------------
// Final layer: out = softmax(A(512x512) @ We(512x10) + be). Warp per row.
// ---------------------------------------------------------------------------
__global__ void __launch_bounds__(256) head_softmax(
    const float* __restrict__ A, const float* __restrict__ We,
    const float* __restrict__ be, float* __restrict__ out)
{
    __shared__ float Ws[512 * 10];
    const int tid = threadIdx.x;
    for (int i = tid; i < 512 * 10; i += 256) Ws[i] = We[i];
    __syncthreads();
    const int lane = tid & 31, w = tid >> 5;
    const int row = blockIdx.x * 8 + w;

    float acc[10];
    #pragma unroll
    for (int c = 0; c < 10; c++) acc[c] = 0.0f;
    for (int k = lane; k < 512; k += 32) {
        float a = A[row * 512 + k];
        #pragma unroll
        for (int c = 0; c < 10; c++) acc[c] = fmaf(a, Ws[k * 10 + c], acc[c]);
    }
    #pragma unroll
    for (int c = 0; c < 10; c++) {
        #pragma unroll
        for (int o = 16; o > 0; o >>= 1)
            acc[c] += __shfl_xor_sync(0xffffffffu, acc[c], o);
    }
    if (lane == 0) {
        float v[10], mx = -1e30f;
        #pragma unroll
        for (int c = 0; c < 10; c++) { v[c] = acc[c] + be[c]; mx = fmaxf(mx, v[c]); }
        float s = 0.0f;
        #pragma unroll
        for (int c = 0; c < 10; c++) { v[c] = __expf(v[c] - mx); s += v[c]; }
        float inv = 1.0f / s;
        #pragma unroll
        for (int c = 0; c < 10; c++) out[row * 10 + c] = v[c] * inv;
    }
}

// ---------------------------------------------------------------------------
extern "C" void kernel_launch(void* const* d_in, const int* in_sizes, int n_in,
                              void* d_out, int out_size)
{
    const int*   src = (const int*)  d_in[0];
    const int*   dst = (const int*)  d_in[1];
    const float* W1  = (const float*)d_in[2];
    const float* b1  = (const float*)d_in[3];
    const float* W2  = (const float*)d_in[4];
    const float* b2  = (const float*)d_in[5];
    const float* Wa  = (const float*)d_in[6];
    const float* ba  = (const float*)d_in[7];
    const float* Wb  = (const float*)d_in[8];
    const float* bb  = (const float*)d_in[9];
    const float* Wc  = (const float*)d_in[10];
    const float* bc  = (const float*)d_in[11];
    const float* Wd  = (const float*)d_in[12];
    const float* bd  = (const float*)d_in[13];
    const float* We  = (const float*)d_in[14];
    const float* be  = (const float*)d_in[15];
    float* out = (float*)d_out;

    float *hg, *x1, *x2, *x3, *x4;
    cudaGetSymbolAddress((void**)&hg, g_hg);
    cudaGetSymbolAddress((void**)&x1, g_x1);
    cudaGetSymbolAddress((void**)&x2, g_x2);
    cudaGetSymbolAddress((void**)&x3, g_x3);
    cudaGetSymbolAddress((void**)&x4, g_x4);

    const int SMEM = 225040;
    cudaFuncSetAttribute(gnn_kernel, cudaFuncAttributeMaxDynamicSharedMemorySize, SMEM);

    gnn_kernel<<<NG, TPB, SMEM>>>(src, dst, W1, b1, W2, b2, hg);

    gemm_bias_relu<<<dim3(512 / 64,  512 / 64), 512>>>(hg, Wa, ba, x1, 512, 128,  512);
    gemm_bias_relu<<<dim3(1024 / 64, 512 / 64), 512>>>(x1, Wb, bb, x2, 512, 512,  1024);
    gemm_bias_relu<<<dim3(1024 / 64, 512 / 64), 512>>>(x2, Wc, bc, x3, 512, 1024, 1024);
    gemm_bias_relu<<<dim3(512 / 64,  512 / 64), 512>>>(x3, Wd, bd, x4, 512, 1024, 512);

    head_softmax<<<64, 256>>>(x4, We, be, out);
}

// round 3
// speedup vs baseline: 2.0086x; 2.0086x over previous
#include <cuda_runtime.h>

#define NG      512
#define NODES   200
#define EDGES   6400
#define HID     128
#define TPB     256

// Scratch (no cudaMalloc allowed)
__device__ float g_hg[NG * HID];
__device__ float g_x1[NG * 512];
__device__ float g_x2[NG * 1024];
__device__ float g_x3[NG * 1024];
__device__ float g_x4[NG * 512];
__device__ float g_x4p[2 * NG * 512];     // split-K partials for layer d

// Piecewise-linear tables for t(a) = (alpha(a)*a + beta(a))
__device__ float g_csorted[128];
__device__ float g_alpha[129 * 128];
__device__ float g_beta[129 * 128];

// ---------------------------------------------------------------------------
// Precompute: h1(a) = relu(a*w1 + b1) (vector in R^128), t(a) = h1(a) @ W2 is
// piecewise linear in the scalar a with breakpoints c_k = -b1[k]/w1[k].
// Build alpha/beta tables for all 129 segments via prefix toggles in sorted
// breakpoint order. 512 threads: 4 chunks x 128 columns.
// ---------------------------------------------------------------------------
__global__ void __launch_bounds__(512) precompute_pwl(
    const float* __restrict__ W1, const float* __restrict__ b1,
    const float* __restrict__ W2)
{
    __shared__ float sc[128];   // breakpoints (by k)
    __shared__ float sw[128], sb[128];
    __shared__ int   sidx[128]; // sorted rank -> k
    __shared__ float ssc[128];  // sorted breakpoints
    const int tid = threadIdx.x;

    if (tid < 128) {
        float w = W1[tid], b = b1[tid];
        sw[tid] = w; sb[tid] = b;
        float c = (w != 0.0f) ? (-b / w) : __int_as_float(0x7f800000); // +inf
        sc[tid] = c;
    }
    __syncthreads();
    if (tid < 128) {
        float c = sc[tid];
        int r = 0;
        for (int j = 0; j < 128; j++) {
            float cj = sc[j];
            if (cj < c || (cj == c && j < tid)) r++;
        }
        sidx[r] = tid;
        ssc[r]  = c;
    }
    __syncthreads();
    if (tid < 128) g_csorted[tid] = ssc[tid];

    const int chunk = tid >> 7;     // 0..3, each owns 32 segments
    const int j     = tid & 127;    // output column
    const int s0    = chunk * 32;

    // Initial (alpha,beta) at segment s0:
    // active = {w>0 & rank<s0} U {w<0 & rank>=s0}; w==0 & b>0 -> beta always.
    float alpha = 0.0f, beta = 0.0f;
    for (int r = 0; r < 128; r++) {
        int k = sidx[r];
        float w = sw[k], b = sb[k];
        float W2kj = W2[k * 128 + j];
        if (w == 0.0f) { if (b > 0.0f) beta += b * W2kj; continue; }
        bool active = (w > 0.0f) ? (r < s0) : (r >= s0);
        if (active) { alpha = fmaf(w, W2kj, alpha); beta = fmaf(b, W2kj, beta); }
    }
    // Serial chain over this chunk's 32 segments
    for (int s = s0; s < s0 + 32; s++) {
        g_alpha[s * 128 + j] = alpha;
        g_beta[s * 128 + j]  = beta;
        int k = sidx[s];
        float w = sw[k], b = sb[k];
        float W2kj = W2[k * 128 + j];
        float f = (w > 0.0f) ? 1.0f : ((w < 0.0f) ? -1.0f : 0.0f);
        alpha = fmaf(f * w, W2kj, alpha);
        beta  = fmaf(f * b, W2kj, beta);
    }
    if (chunk == 3) {
        g_alpha[128 * 128 + j] = alpha;
        g_beta[128 * 128 + j]  = beta;
    }
}

// ---------------------------------------------------------------------------
// Per-graph GNN kernel (256 threads, 2 CTAs/SM):
// degrees -> CSR -> scalar layer-1 agg -> t_i via PWL table lookup ->
// layer-2 CSR gather + fused mean pool.
// SMEM: t[200*128] f | s_s,s_a,s_ii,s_io[200] | cnt[204] cur[204] i32 |
//       seg8[208] u8 | csr[6400] u8  = 113,840 B  (2 per SM)
// ---------------------------------------------------------------------------
__global__ void __launch_bounds__(TPB, 2) gnn_kernel(
    const int*   __restrict__ src, const int*   __restrict__ dst,
    const float* __restrict__ b2,  float* __restrict__ hg)
{
    extern __shared__ float sf[];
    float* t    = sf;                              // 25600 floats
    float* s_s  = sf + 25600;                      // 200
    float* s_a  = s_s + NODES;                     // 200
    float* s_ii = s_a + NODES;                     // 200
    float* s_io = s_ii + NODES;                    // 200
    int*   cnt  = (int*)(s_io + NODES);            // 204
    int*   cur  = cnt + 204;                       // 204 (first: out-degree)
    unsigned char* seg8 = (unsigned char*)(cur + 204); // 208
    unsigned char* csr  = seg8 + 208;              // 6400

    const int tid   = threadIdx.x;
    const int g     = blockIdx.x;
    const int ebase = g * EDGES;
    const int nbase = g * NODES;

    // --- degrees (cnt = in-deg, cur = out-deg) ---
    for (int i = tid; i < 204; i += TPB) { cnt[i] = 0; cur[i] = 0; }
    __syncthreads();
    for (int e = tid; e < EDGES; e += TPB) {
        int sl = src[ebase + e] - nbase;
        int dl = dst[ebase + e] - nbase;
        atomicAdd(&cnt[dl], 1);
        atomicAdd(&cur[sl], 1);
    }
    __syncthreads();
    for (int i = tid; i < NODES; i += TPB) {
        float idg = (float)cnt[i];
        float odg = (float)cur[i];
        float ii = rsqrtf(fmaxf(idg, 1.0f));
        float io = rsqrtf(fmaxf(odg, 1.0f));
        s_ii[i] = ii;
        s_io[i] = io;
        s_s[i]  = idg * io;
    }
    __syncthreads();
    // --- warp-parallel exclusive scan of cnt; cur <- offsets ---
    if (tid < 32) {
        const int PER = 7;
        int base = tid * PER;
        int vals[PER];
        int s = 0;
        #pragma unroll
        for (int j = 0; j < PER; j++) {
            int i = base + j;
            int c = (i < NODES) ? cnt[i] : 0;
            vals[j] = c; s += c;
        }
        int pre = s;
        #pragma unroll
        for (int o = 1; o < 32; o <<= 1) {
            int tt = __shfl_up_sync(0xffffffffu, pre, o);
            if (tid >= o) pre += tt;
        }
        int run = pre - s;
        #pragma unroll
        for (int j = 0; j < PER; j++) {
            int i = base + j;
            if (i < NODES) { cnt[i] = run; cur[i] = run; run += vals[j]; }
        }
        if (tid == 31) cnt[NODES] = run;
    }
    __syncthreads();
    // --- CSR fill: src local ids grouped by dst ---
    for (int e = tid; e < EDGES; e += TPB) {
        int sl = src[ebase + e] - nbase;
        int dl = dst[ebase + e] - nbase;
        int p  = atomicAdd(&cur[dl], 1);
        csr[p] = (unsigned char)sl;
    }
    __syncthreads();
    // --- layer-1 scalar aggregation + segment lookup ---
    for (int d = tid; d < NODES; d += TPB) {
        float sum = 0.0f;
        int p0 = cnt[d], p1 = cnt[d + 1];
        for (int p = p0; p < p1; p++) sum += s_s[csr[p]];
        float a = sum * s_ii[d];
        s_a[d] = a;
        // binary search: seg = #{ c_sorted < a }
        int lo = 0, hi = 128;
        while (lo < hi) {
            int m = (lo + hi) >> 1;
            if (g_csorted[m] < a) lo = m + 1; else hi = m;
        }
        seg8[d] = (unsigned char)lo;
    }
    __syncthreads();
    // --- t_i = (alpha_s * a_i + beta_s) * inv_out_i ---
    for (int idx = tid; idx < NODES * 32; idx += TPB) {
        int i = idx >> 5, q = idx & 31;
        float a  = s_a[i];
        float io = s_io[i];
        int   s  = seg8[i];
        float4 al = ((const float4*)(g_alpha + s * 128))[q];
        float4 be = ((const float4*)(g_beta  + s * 128))[q];
        float4 o;
        o.x = fmaf(al.x, a, be.x) * io;
        o.y = fmaf(al.y, a, be.y) * io;
        o.z = fmaf(al.z, a, be.z) * io;
        o.w = fmaf(al.w, a, be.w) * io;
        ((float4*)t)[idx] = o;
    }
    __syncthreads();
    // --- layer-2 gather + relu + fused mean pool (warp per dst) ---
    const int tx = tid & 31;   // 32 float4 col groups
    const int w  = tid >> 5;   // 8 warps
    {
        float4 bb2 = ((const float4*)b2)[tx];
        float4 pacc = {0, 0, 0, 0};
        for (int d = w; d < NODES; d += 8) {
            int p0 = cnt[d], p1 = cnt[d + 1];
            float4 acc = {0, 0, 0, 0};
            for (int p = p0; p < p1; ++p) {
                int sv = csr[p];
                float4 v = ((const float4*)t)[sv * 32 + tx];
                acc.x += v.x; acc.y += v.y; acc.z += v.z; acc.w += v.w;
            }
            float ii = s_ii[d];
            pacc.x += fmaxf(fmaf(acc.x, ii, bb2.x), 0.0f);
            pacc.y += fmaxf(fmaf(acc.y, ii, bb2.y), 0.0f);
            pacc.z += fmaxf(fmaf(acc.z, ii, bb2.z), 0.0f);
            pacc.w += fmaxf(fmaf(acc.w, ii, bb2.w), 0.0f);
        }
        __syncthreads();                       // done reading t
        ((float4*)t)[w * 32 + tx] = pacc;      // 8 warp partials
    }
    __syncthreads();
    if (tid < HID) {
        float s = 0.0f;
        #pragma unroll
        for (int c = 0; c < 8; c++) s += t[c * HID + tid];
        hg[g * HID + tid] = s * (1.0f / 200.0f);
    }
}

// ---------------------------------------------------------------------------
// Double-buffered fp32 GEMM: C = [relu](A @ W + bias). 64x64 tile, 256 thr,
// 4x4 per thread. Optional split-K via blockIdx.z (K = per-chunk size,
// zCstride = output offset per z). bias==nullptr -> raw accumulation out.
// ---------------------------------------------------------------------------
__global__ void __launch_bounds__(256) gemm_db(
    const float* __restrict__ A, int lda,
    const float* __restrict__ W,
    const float* __restrict__ bias,
    float* __restrict__ C,
    int K, int Nc, int do_relu, int zCstride)
{
    __shared__ float As[2][64 * 16];
    __shared__ float Ws[2][16 * 64];
    const int tid = threadIdx.x;
    const int tx = tid & 15, ty = tid >> 4;
    const int row0 = blockIdx.y * 64, col0 = blockIdx.x * 64;

    A += (size_t)blockIdx.z * K;            // split-K column offset
    W += (size_t)blockIdx.z * K * Nc;       // split-K row offset
    C += (size_t)blockIdx.z * zCstride;

    const int ar = tid >> 2, akq = (tid & 3) * 4;   // A loader coords
    const int wk = tid >> 4, wc = (tid & 15) * 4;   // W loader coords

    float4 ga = *(const float4*)(A + (size_t)(row0 + ar) * lda + akq);
    float4 gw = *(const float4*)(W + (size_t)wk * Nc + col0 + wc);
    ((float4*)As[0])[tid] = ga;
    ((float4*)Ws[0])[tid] = gw;
    __syncthreads();

    float4 acc[4] = {{0,0,0,0},{0,0,0,0},{0,0,0,0},{0,0,0,0}};
    const int ntiles = K >> 4;
    int buf = 0;
    for (int kt = 0; kt < ntiles; kt++) {
        if (kt + 1 < ntiles) {
            ga = *(const float4*)(A + (size_t)(row0 + ar) * lda + (kt + 1) * 16 + akq);
            gw = *(const float4*)(W + (size_t)((kt + 1) * 16 + wk) * Nc + col0 + wc);
        }
        #pragma unroll
        for (int kk = 0; kk < 16; kk++) {
            float4 w = ((float4*)Ws[buf])[kk * 16 + tx];
            #pragma unroll
            for (int i = 0; i < 4; i++) {
                float a = As[buf][(ty * 4 + i) * 16 + kk];
                acc[i].x = fmaf(a, w.x, acc[i].x);
                acc[i].y = fmaf(a, w.y, acc[i].y);
                acc[i].z = fmaf(a, w.z, acc[i].z);
                acc[i].w = fmaf(a, w.w, acc[i].w);
            }
        }
        if (kt + 1 < ntiles) {
            ((float4*)As[buf ^ 1])[tid] = ga;
            ((float4*)Ws[buf ^ 1])[tid] = gw;
        }
        __syncthreads();
        buf ^= 1;
    }
    float4 bv = {0, 0, 0, 0};
    if (bias) bv = *(const float4*)(bias + col0 + tx * 4);
    #pragma unroll
    for (int i = 0; i < 4; i++) {
        float4 o = acc[i];
        o.x += bv.x; o.y += bv.y; o.z += bv.z; o.w += bv.w;
        if (do_relu) {
            o.x = fmaxf(o.x, 0.0f); o.y = fmaxf(o.y, 0.0f);
            o.z = fmaxf(o.z, 0.0f); o.w = fmaxf(o.w, 0.0f);
        }
        *(float4*)(C + (size_t)(row0 + ty * 4 + i) * Nc + col0 + tx * 4) = o;
    }
}

// Combine split-K partials: x = relu(p0 + p1 + bias)
__global__ void __launch_bounds__(256) combine_relu(
    const float* __restrict__ p, const float* __restrict__ bias,
    float* __restrict__ C, int Nc, int total4)
{
    int idx = blockIdx.x * 256 + threadIdx.x;
    if (idx >= total4) return;
    const int nq = Nc >> 2;
    float4 a = ((const float4*)p)[idx];
    float4 b = ((const float4*)p)[idx + total4];
    float4 bv = ((const float4*)bias)[idx % nq];
    float4 o;
    o.x = fmaxf(a.x + b.x + bv.x, 0.0f);
    o.y = fmaxf(a.y + b.y + bv.y, 0.0f);
    o.z = fmaxf(a.z + b.z + bv.z, 0.0f);
    o.w = fmaxf(a.w + b.w + bv.w, 0.0f);
    ((float4*)C)[idx] = o;
}

// ---------------------------------------------------------------------------
// Final layer: out = softmax(A(512x512) @ We(512x10) + be). Warp per row.
// ---------------------------------------------------------------------------
__global__ void __launch_bounds__(256) head_softmax(
    const float* __restrict__ A, const float* __restrict__ We,
    const float* __restrict__ be, float* __restrict__ out)
{
    __shared__ float Ws[512 * 10];
    const int tid = threadIdx.x;
    for (int i = tid; i < 512 * 10; i += 256) Ws[i] = We[i];
    __syncthreads();
    const int lane = tid & 31, w = tid >> 5;
    const int row = blockIdx.x * 8 + w;

    float acc[10];
    #pragma unroll
    for (int c = 0; c < 10; c++) acc[c] = 0.0f;
    for (int k = lane; k < 512; k += 32) {
        float a = A[row * 512 + k];
        #pragma unroll
        for (int c = 0; c < 10; c++) acc[c] = fmaf(a, Ws[k * 10 + c], acc[c]);
    }
    #pragma unroll
    for (int c = 0; c < 10; c++) {
        #pragma unroll
        for (int o = 16; o > 0; o >>= 1)
            acc[c] += __shfl_xor_sync(0xffffffffu, acc[c], o);
    }
    if (lane == 0) {
        float v[10], mx = -1e30f;
        #pragma unroll
        for (int c = 0; c < 10; c++) { v[c] = acc[c] + be[c]; mx = fmaxf(mx, v[c]); }
        float s = 0.0f;
        #pragma unroll
        for (int c = 0; c < 10; c++) { v[c] = __expf(v[c] - mx); s += v[c]; }
        float inv = 1.0f / s;
        #pragma unroll
        for (int c = 0; c < 10; c++) out[row * 10 + c] = v[c] * inv;
    }
}

// ---------------------------------------------------------------------------
extern "C" void kernel_launch(void* const* d_in, const int* in_sizes, int n_in,
                              void* d_out, int out_size)
{
    const int*   src = (const int*)  d_in[0];
    const int*   dst = (const int*)  d_in[1];
    const float* W1  = (const float*)d_in[2];
    const float* b1  = (const float*)d_in[3];
    const float* W2  = (const float*)d_in[4];
    const float* b2  = (const float*)d_in[5];
    const float* Wa  = (const float*)d_in[6];
    const float* ba  = (const float*)d_in[7];
    const float* Wb  = (const float*)d_in[8];
    const float* bb  = (const float*)d_in[9];
    const float* Wc  = (const float*)d_in[10];
    const float* bc  = (const float*)d_in[11];
    const float* Wd  = (const float*)d_in[12];
    const float* bd  = (const float*)d_in[13];
    const float* We  = (const float*)d_in[14];
    const float* be  = (const float*)d_in[15];
    float* out = (float*)d_out;

    float *hg, *x1, *x2, *x3, *x4, *x4p;
    cudaGetSymbolAddress((void**)&hg,  g_hg);
    cudaGetSymbolAddress((void**)&x1,  g_x1);
    cudaGetSymbolAddress((void**)&x2,  g_x2);
    cudaGetSymbolAddress((void**)&x3,  g_x3);
    cudaGetSymbolAddress((void**)&x4,  g_x4);
    cudaGetSymbolAddress((void**)&x4p, g_x4p);

    const int SMEM = 113840;
    cudaFuncSetAttribute(gnn_kernel, cudaFuncAttributeMaxDynamicSharedMemorySize, SMEM);

    precompute_pwl<<<1, 512>>>(W1, b1, W2);
    gnn_kernel<<<NG, TPB, SMEM>>>(src, dst, b2, hg);

    // MLP
    gemm_db<<<dim3(8, 8, 1),  256>>>(hg, 128,  Wa, ba, x1, 128,  512,  1, 0);
    gemm_db<<<dim3(16, 8, 1), 256>>>(x1, 512,  Wb, bb, x2, 512,  1024, 1, 0);
    gemm_db<<<dim3(16, 8, 1), 256>>>(x2, 1024, Wc, bc, x3, 1024, 1024, 1, 0);
    // layer d split-K x2: 128 CTAs
    gemm_db<<<dim3(8, 8, 2),  256>>>(x3, 1024, Wd, nullptr, x4p, 512, 512, 0, 512 * 512);
    combine_relu<<<(512 * 512 / 4 + 255) / 256, 256>>>(x4p, bd, x4, 512, 512 * 512 / 4);

    head_softmax<<<64, 256>>>(x4, We, be, out);
}